// round 7
// baseline (speedup 1.0000x reference)
#include <cuda_runtime.h>

#define CH     512
#define HW     4096        // 64*64
#define NPIX   32768       // 8 * 4096

// Static device scratch (no dynamic allocation allowed).
__device__ float g_recon[NPIX];
__device__ float g_ref[NPIX];

// ---- packed f32x2 helpers (Blackwell FFMA2 path, PTX-only) -----------------
typedef unsigned long long ull;
__device__ __forceinline__ ull pk2(float lo, float hi) {
    ull r; asm("mov.b64 %0, {%1, %2};" : "=l"(r) : "f"(lo), "f"(hi)); return r;
}
__device__ __forceinline__ void unpk2(ull v, float& lo, float& hi) {
    asm("mov.b64 {%0, %1}, %2;" : "=f"(lo), "=f"(hi) : "l"(v));
}
__device__ __forceinline__ ull fma2(ull a, ull b, ull c) {
    ull d; asm("fma.rn.f32x2 %0, %1, %2, %3;" : "=l"(d) : "l"(a), "l"(b), "l"(c));
    return d;
}
__device__ __forceinline__ ull mul2(ull a, ull b) {
    ull d; asm("mul.rn.f32x2 %0, %1, %2;" : "=l"(d) : "l"(a), "l"(b)); return d;
}

// ---------------------------------------------------------------------------
// Kernel A (fused dot + reduce) — unchanged from R6 (measured near DRAM roof).
// ---------------------------------------------------------------------------
__global__ void __launch_bounds__(256) k_fused(
        const float* __restrict__ spade, const float* __restrict__ x,
        const float* __restrict__ w1, const float* __restrict__ w2,
        const float* __restrict__ b1, const float* __restrict__ b2) {
    __shared__ float2 ws[CH];                 // (w1, w2) pairs
    __shared__ float4 red1[16][16];           // [group][float4 slot]
    __shared__ float4 red2[16][16];
    const int t = threadIdx.x;
    for (int c = t; c < CH; c += 256) ws[c] = make_float2(w1[c], w2[c]);
    __syncthreads();

    const int pt  = blockIdx.x;               // 64-px tile index (0..511)
    const int b   = pt >> 6;                  // batch
    const int hw0 = (pt & 63) * 64;           // tile base within the image
    const int i   = t & 15;                   // float4 slot (4 px)
    const int j   = t >> 4;                   // channel group (32 ch)

    const size_t base = (size_t)b * CH * HW + (size_t)(j * 32) * HW + hw0 + i * 4;
    const float4* fp = (const float4*)(spade + base);
    const float4* xp = (const float4*)(x + base);
    const float2* wp = ws + j * 32;

    float4 a1 = make_float4(0.f, 0.f, 0.f, 0.f);
    float4 a2 = make_float4(0.f, 0.f, 0.f, 0.f);
    #pragma unroll 8
    for (int c = 0; c < 32; c++) {
        float4 f = __ldcs(fp + (size_t)c * (HW / 4));
        float4 v = __ldcs(xp + (size_t)c * (HW / 4));
        const float2 w = wp[c];
        a1.x += f.x * w.x; a1.y += f.y * w.x; a1.z += f.z * w.x; a1.w += f.w * w.x;
        a2.x += v.x * w.y; a2.y += v.y * w.y; a2.z += v.z * w.y; a2.w += v.w * w.y;
    }
    red1[j][i] = a1;
    red2[j][i] = a2;
    __syncthreads();

    if (t < 16) {
        float4 s = make_float4(0.f, 0.f, 0.f, 0.f);
        #pragma unroll
        for (int g = 0; g < 16; g++) {
            const float4 a = red1[g][t];
            s.x += a.x; s.y += a.y; s.z += a.z; s.w += a.w;
        }
        const float bb = b1[0];
        s.x = fmaxf(s.x + bb, 0.f); s.y = fmaxf(s.y + bb, 0.f);
        s.z = fmaxf(s.z + bb, 0.f); s.w = fmaxf(s.w + bb, 0.f);
        *(float4*)&g_recon[pt * 64 + t * 4] = s;
    } else if (t >= 32 && t < 48) {
        const int i2 = t - 32;
        float4 s = make_float4(0.f, 0.f, 0.f, 0.f);
        #pragma unroll
        for (int g = 0; g < 16; g++) {
            const float4 a = red2[g][i2];
            s.x += a.x; s.y += a.y; s.z += a.z; s.w += a.w;
        }
        const float bb = b2[0];
        s.x = fmaxf(s.x + bb, 0.f); s.y = fmaxf(s.y + bb, 0.f);
        s.z = fmaxf(s.z + bb, 0.f); s.w = fmaxf(s.w + bb, 0.f);
        *(float4*)&g_ref[pt * 64 + i2 * 4] = s;
    }
}

// ---------------------------------------------------------------------------
// Kernel B (k_match v3): grid 1024, block = 8 patches. 8 warps: warp w serves
// patch pair (w>>1) over row-half (w&1): 32-row sweep for 2 patches, shared
// LDS row loads. Cheap per-row argmax: rv = fmaxf(y0,y1), strict-> update of
// {bv, rowIdx, y0@best}; the +-1 column bit is decoded once after the sweep.
// Halves are combined in SMEM (disjoint index ranges keep first-occurrence
// semantics). Gather/write from the still-resident SMEM tile.
// ---------------------------------------------------------------------------
__global__ void __launch_bounds__(256) k_match(float* __restrict__ out) {
    __shared__ float Ra[65][68];   // recon tile; row 64 / cols>=64 are zero
    __shared__ float sv[8][2];     // [local patch][row half] best value
    __shared__ int   si[8][2];     // [local patch][row half] best flat idx
    const int t    = threadIdx.x;
    const int b    = blockIdx.x >> 7;
    const int grp  = blockIdx.x & 127;      // 128 groups of 8 patches
    const float* rb = g_recon + b * HW;

    for (int i = t; i < 65 * 68; i += 256) {
        const int row = i / 68;
        const int col = i - row * 68;
        Ra[row][col] = (row < 64 && col < 64) ? rb[row * 64 + col] : 0.f;
    }
    __syncthreads();

    const int lane = t & 31;
    const int w    = t >> 5;
    const int rh   = w & 1;                 // row half: 0 -> rows 0-31, 1 -> 32-63
    const int pr   = w >> 1;                // patch pair 0..3
    const float* refb = g_ref + b * HW;

    const int lA = grp * 8 + pr * 2;
    const int lB = lA + 1;
    const int piA = lA >> 5, pjA = lA & 31;
    const int piB = lB >> 5, pjB = lB & 31;

    const float a00 = refb[(2 * piA) * 64 + 2 * pjA];
    const float a01 = refb[(2 * piA) * 64 + 2 * pjA + 1];
    const float a10 = refb[(2 * piA + 1) * 64 + 2 * pjA];
    const float a11 = refb[(2 * piA + 1) * 64 + 2 * pjA + 1];
    const float b00 = refb[(2 * piB) * 64 + 2 * pjB];
    const float b01 = refb[(2 * piB) * 64 + 2 * pjB + 1];
    const float b10 = refb[(2 * piB + 1) * 64 + 2 * pjB];
    const float b11 = refb[(2 * piB + 1) * 64 + 2 * pjB + 1];
    const ull ca00 = pk2(a00, a00), ca01 = pk2(a01, a01);
    const ull ca10 = pk2(a10, a10), ca11 = pk2(a11, a11);
    const ull cb00 = pk2(b00, b00), cb01 = pk2(b01, b01);
    const ull cb10 = pk2(b10, b10), cb11 = pk2(b11, b11);

    const int q  = lane * 2;
    const int p0 = rh * 32;

    ull cur01 = *(const ull*)&Ra[p0][q];
    float r0h, r1h; unpk2(cur01, r0h, r1h);
    ull v12 = pk2(r1h, Ra[p0][q + 2]);

    // accumulators: value, row-base flat idx, y0 value at best row
    float bvA = -1.f, byA = 0.f;  int biA = 0;
    float bvB = -1.f, byB = 0.f;  int biB = 0;
    int idx = (p0 << 6) + q;

    #pragma unroll 4
    for (int p = p0; p < p0 + 32; p++) {
        const ull nxt01 = *(const ull*)&Ra[p + 1][q];
        const ull nxt23 = *(const ull*)&Ra[p + 1][q + 2];
        float n0, n1; unpk2(nxt01, n0, n1);
        float n2, nx; unpk2(nxt23, n2, nx);
        const ull w12 = pk2(n1, n2);

        const ull yA = fma2(ca11, w12, fma2(ca10, nxt01,
                       fma2(ca01, v12, mul2(ca00, cur01))));
        const ull yB = fma2(cb11, w12, fma2(cb10, nxt01,
                       fma2(cb01, v12, mul2(cb00, cur01))));

        float yA0, yA1; unpk2(yA, yA0, yA1);
        const float rvA = fmaxf(yA0, yA1);
        if (rvA > bvA) { bvA = rvA; biA = idx; byA = yA0; }

        float yB0, yB1; unpk2(yB, yB0, yB1);
        const float rvB = fmaxf(yB0, yB1);
        if (rvB > bvB) { bvB = rvB; biB = idx; byB = yB0; }

        cur01 = nxt01;
        v12   = w12;
        idx  += 64;
    }

    // Decode the +-1 column bit (bv == by0 -> y0 -> earlier column on tie).
    int riA = biA + ((bvA > byA) ? 1 : 0);
    int riB = biB + ((bvB > byB) ? 1 : 0);

    // Warp argmax per patch; ties -> smallest flat index (jnp.argmax).
    #pragma unroll
    for (int off = 16; off; off >>= 1) {
        const float vA = __shfl_down_sync(0xffffffffu, bvA, off);
        const int   iA = __shfl_down_sync(0xffffffffu, riA, off);
        if (vA > bvA || (vA == bvA && iA < riA)) { bvA = vA; riA = iA; }
        const float vB = __shfl_down_sync(0xffffffffu, bvB, off);
        const int   iB = __shfl_down_sync(0xffffffffu, riB, off);
        if (vB > bvB || (vB == bvB && iB < riB)) { bvB = vB; riB = iB; }
    }

    if (lane == 0) {
        sv[pr * 2 + 0][rh] = bvA;  si[pr * 2 + 0][rh] = riA;
        sv[pr * 2 + 1][rh] = bvB;  si[pr * 2 + 1][rh] = riB;
    }
    __syncthreads();

    // Combine halves + gather + write (8 threads, one per patch).
    if (t < 8) {
        float bv = sv[t][0];
        int   bi = si[t][0];
        const float v1 = sv[t][1];
        const int   i1 = si[t][1];
        // half-1 indices are all larger, so ties keep half 0 (first occurrence)
        if (v1 > bv) { bv = v1; bi = i1; }

        const int l  = grp * 8 + t;
        const int pi = l >> 5, pj = l & 31;
        const int g  = bi >> 2;               // offset // 4
        const int gi = g >> 5, gj = g & 31;
        float* o = out + b * HW + (2 * pi) * 64 + 2 * pj;
        o[0]  = Ra[2 * gi][2 * gj];
        o[1]  = Ra[2 * gi][2 * gj + 1];
        o[64] = Ra[2 * gi + 1][2 * gj];
        o[65] = Ra[2 * gi + 1][2 * gj + 1];
    }
}

extern "C" void kernel_launch(void* const* d_in, const int* in_sizes, int n_in,
                              void* d_out, int out_size) {
    const float* spade = (const float*)d_in[0];
    const float* x     = (const float*)d_in[1];
    const float* w1    = (const float*)d_in[2];
    const float* b1    = (const float*)d_in[3];
    const float* w2    = (const float*)d_in[4];
    const float* b2    = (const float*)d_in[5];
    float* out = (float*)d_out;

    k_fused<<<512, 256>>>(spade, x, w1, w2, b1, b2);
    k_match<<<1024, 256>>>(out);
}

// round 8
// speedup vs baseline: 1.0437x; 1.0437x over previous
#include <cuda_runtime.h>

#define CH     512
#define HW     4096        // 64*64
#define NPIX   32768       // 8 * 4096

// Static device scratch (no dynamic allocation allowed).
__device__ float g_recon[NPIX];
__device__ float g_ref[NPIX];

// ---- packed f32x2 helpers (Blackwell FFMA2 path, PTX-only) -----------------
typedef unsigned long long ull;
__device__ __forceinline__ ull pk2(float lo, float hi) {
    ull r; asm("mov.b64 %0, {%1, %2};" : "=l"(r) : "f"(lo), "f"(hi)); return r;
}
__device__ __forceinline__ void unpk2(ull v, float& lo, float& hi) {
    asm("mov.b64 {%0, %1}, %2;" : "=f"(lo), "=f"(hi) : "l"(v));
}
__device__ __forceinline__ ull fma2(ull a, ull b, ull c) {
    ull d; asm("fma.rn.f32x2 %0, %1, %2, %3;" : "=l"(d) : "l"(a), "l"(b), "l"(c));
    return d;
}
__device__ __forceinline__ ull mul2(ull a, ull b) {
    ull d; asm("mul.rn.f32x2 %0, %1, %2;" : "=l"(d) : "l"(a), "l"(b)); return d;
}

// ---------------------------------------------------------------------------
// Kernel A (fused dot + reduce) — unchanged (measured near DRAM roof).
// ---------------------------------------------------------------------------
__global__ void __launch_bounds__(256) k_fused(
        const float* __restrict__ spade, const float* __restrict__ x,
        const float* __restrict__ w1, const float* __restrict__ w2,
        const float* __restrict__ b1, const float* __restrict__ b2) {
    __shared__ float2 ws[CH];                 // (w1, w2) pairs
    __shared__ float4 red1[16][16];           // [group][float4 slot]
    __shared__ float4 red2[16][16];
    const int t = threadIdx.x;
    for (int c = t; c < CH; c += 256) ws[c] = make_float2(w1[c], w2[c]);
    __syncthreads();

    const int pt  = blockIdx.x;               // 64-px tile index (0..511)
    const int b   = pt >> 6;                  // batch
    const int hw0 = (pt & 63) * 64;           // tile base within the image
    const int i   = t & 15;                   // float4 slot (4 px)
    const int j   = t >> 4;                   // channel group (32 ch)

    const size_t base = (size_t)b * CH * HW + (size_t)(j * 32) * HW + hw0 + i * 4;
    const float4* fp = (const float4*)(spade + base);
    const float4* xp = (const float4*)(x + base);
    const float2* wp = ws + j * 32;

    float4 a1 = make_float4(0.f, 0.f, 0.f, 0.f);
    float4 a2 = make_float4(0.f, 0.f, 0.f, 0.f);
    #pragma unroll 8
    for (int c = 0; c < 32; c++) {
        float4 f = __ldcs(fp + (size_t)c * (HW / 4));
        float4 v = __ldcs(xp + (size_t)c * (HW / 4));
        const float2 w = wp[c];
        a1.x += f.x * w.x; a1.y += f.y * w.x; a1.z += f.z * w.x; a1.w += f.w * w.x;
        a2.x += v.x * w.y; a2.y += v.y * w.y; a2.z += v.z * w.y; a2.w += v.w * w.y;
    }
    red1[j][i] = a1;
    red2[j][i] = a2;
    __syncthreads();

    if (t < 16) {
        float4 s = make_float4(0.f, 0.f, 0.f, 0.f);
        #pragma unroll
        for (int g = 0; g < 16; g++) {
            const float4 a = red1[g][t];
            s.x += a.x; s.y += a.y; s.z += a.z; s.w += a.w;
        }
        const float bb = b1[0];
        s.x = fmaxf(s.x + bb, 0.f); s.y = fmaxf(s.y + bb, 0.f);
        s.z = fmaxf(s.z + bb, 0.f); s.w = fmaxf(s.w + bb, 0.f);
        *(float4*)&g_recon[pt * 64 + t * 4] = s;
    } else if (t >= 32 && t < 48) {
        const int i2 = t - 32;
        float4 s = make_float4(0.f, 0.f, 0.f, 0.f);
        #pragma unroll
        for (int g = 0; g < 16; g++) {
            const float4 a = red2[g][i2];
            s.x += a.x; s.y += a.y; s.z += a.z; s.w += a.w;
        }
        const float bb = b2[0];
        s.x = fmaxf(s.x + bb, 0.f); s.y = fmaxf(s.y + bb, 0.f);
        s.z = fmaxf(s.z + bb, 0.f); s.w = fmaxf(s.w + bb, 0.f);
        *(float4*)&g_ref[pt * 64 + i2 * 4] = s;
    }
}

// ---------------------------------------------------------------------------
// Kernel B (k_match v4): 512 blocks = (b, 16-patch group). 8 warps = 4 patch
// quads x 2 row halves. Each warp sweeps 32 rows for 4 patches sharing the
// LDS row loads. Per patch per row only (value, row-base idx) is tracked
// (FMNMX + FSETP + SEL + FMNMX); the +-1 column bit is decoded ONCE per patch
// by bit-exact recomputation at the winning row. Halves combined in SMEM.
// jnp.argmax first-occurrence tie semantics preserved (min flat idx).
// ---------------------------------------------------------------------------
__global__ void __launch_bounds__(256) k_match(float* __restrict__ out) {
    __shared__ float Ra[65][68];   // recon tile; row 64 / cols>=64 are zero
    __shared__ float sv[16][2];    // [local patch][row half] best value
    __shared__ int   si[16][2];    // [local patch][row half] best row-base idx
    const int t    = threadIdx.x;
    const int b    = blockIdx.x >> 6;
    const int grp  = blockIdx.x & 63;       // 64 groups of 16 patches
    const float* rb = g_recon + b * HW;

    for (int i = t; i < 65 * 68; i += 256) {
        const int row = i / 68;
        const int col = i - row * 68;
        Ra[row][col] = (row < 64 && col < 64) ? rb[row * 64 + col] : 0.f;
    }
    __syncthreads();

    const int lane = t & 31;
    const int w    = t >> 5;
    const int rh   = w & 1;                 // row half: rows [rh*32, rh*32+32)
    const int pq   = w >> 1;                // patch quad 0..3
    const float* refb = g_ref + b * HW;

    const int l0 = grp * 16 + pq * 4;       // first of 4 patches for this warp

    // Load 2x2 coefficients for 4 patches (broadcast LDGs), pack for FFMA2.
    ull cc[4][4];
    #pragma unroll
    for (int pp = 0; pp < 4; pp++) {
        const int l  = l0 + pp;
        const int pi = l >> 5, pj = l & 31;
        const float c00 = refb[(2 * pi) * 64 + 2 * pj];
        const float c01 = refb[(2 * pi) * 64 + 2 * pj + 1];
        const float c10 = refb[(2 * pi + 1) * 64 + 2 * pj];
        const float c11 = refb[(2 * pi + 1) * 64 + 2 * pj + 1];
        cc[pp][0] = pk2(c00, c00);
        cc[pp][1] = pk2(c01, c01);
        cc[pp][2] = pk2(c10, c10);
        cc[pp][3] = pk2(c11, c11);
    }

    const int q  = lane * 2;
    const int p0 = rh * 32;

    ull cur01 = *(const ull*)&Ra[p0][q];
    float r0h, r1h; unpk2(cur01, r0h, r1h);
    ull v12 = pk2(r1h, Ra[p0][q + 2]);

    float bv[4] = {-1.f, -1.f, -1.f, -1.f};
    int   bi[4] = {0, 0, 0, 0};
    int   idx   = (p0 << 6) + q;            // row-base flat idx for this lane

    #pragma unroll 4
    for (int p = p0; p < p0 + 32; p++) {
        const ull nxt01 = *(const ull*)&Ra[p + 1][q];
        const ull nxt23 = *(const ull*)&Ra[p + 1][q + 2];
        float n0, n1; unpk2(nxt01, n0, n1);
        float n2, nx; unpk2(nxt23, n2, nx);
        const ull w12 = pk2(n1, n2);

        #pragma unroll
        for (int pp = 0; pp < 4; pp++) {
            const ull y = fma2(cc[pp][3], w12, fma2(cc[pp][2], nxt01,
                          fma2(cc[pp][1], v12, mul2(cc[pp][0], cur01))));
            float y0, y1; unpk2(y, y0, y1);
            const float rv = fmaxf(y0, y1);
            if (rv > bv[pp]) { bi[pp] = idx; }
            bv[pp] = fmaxf(bv[pp], rv);
        }
        cur01 = nxt01;
        v12   = w12;
        idx  += 64;
    }

    // Warp argmax per patch; ties -> smallest flat idx (row-major order).
    #pragma unroll
    for (int pp = 0; pp < 4; pp++) {
        float v = bv[pp]; int i0 = bi[pp];
        #pragma unroll
        for (int off = 16; off; off >>= 1) {
            const float v2 = __shfl_down_sync(0xffffffffu, v, off);
            const int   i2 = __shfl_down_sync(0xffffffffu, i0, off);
            if (v2 > v || (v2 == v && i2 < i0)) { v = v2; i0 = i2; }
        }
        if (lane == 0) { sv[pq * 4 + pp][rh] = v; si[pq * 4 + pp][rh] = i0; }
    }
    __syncthreads();

    // Combine halves, decode the column bit (bit-exact recompute), gather.
    if (t < 16) {
        float v = sv[t][0];
        int   bi2 = si[t][0];
        const float v1 = sv[t][1];
        const int   i1 = si[t][1];
        if (v1 > v) { v = v1; bi2 = i1; }    // half-1 rows all larger -> ties keep half 0

        const int l  = grp * 16 + t;
        const int pi = l >> 5, pj = l & 31;
        const float c00 = refb[(2 * pi) * 64 + 2 * pj];
        const float c01 = refb[(2 * pi) * 64 + 2 * pj + 1];
        const float c10 = refb[(2 * pi + 1) * 64 + 2 * pj];
        const float c11 = refb[(2 * pi + 1) * 64 + 2 * pj + 1];

        const int pr = bi2 >> 6;             // winning row
        const int qb = bi2 & 63;             // winning column pair base
        // recompute y0 with identical fma ordering as the packed lo lane
        const float r0 = Ra[pr][qb],     r1 = Ra[pr][qb + 1];
        const float n0 = Ra[pr + 1][qb], n1 = Ra[pr + 1][qb + 1];
        float y0 = c00 * r0;
        y0 = fmaf(c01, r1, y0);
        y0 = fmaf(c10, n0, y0);
        y0 = fmaf(c11, n1, y0);
        const int besti = bi2 + ((y0 == v) ? 0 : 1);  // earlier col on tie

        const int g  = besti >> 2;           // offset // 4
        const int gi = g >> 5, gj = g & 31;
        float* o = out + b * HW + (2 * pi) * 64 + 2 * pj;
        o[0]  = Ra[2 * gi][2 * gj];
        o[1]  = Ra[2 * gi][2 * gj + 1];
        o[64] = Ra[2 * gi + 1][2 * gj];
        o[65] = Ra[2 * gi + 1][2 * gj + 1];
    }
}

extern "C" void kernel_launch(void* const* d_in, const int* in_sizes, int n_in,
                              void* d_out, int out_size) {
    const float* spade = (const float*)d_in[0];
    const float* x     = (const float*)d_in[1];
    const float* w1    = (const float*)d_in[2];
    const float* b1    = (const float*)d_in[3];
    const float* w2    = (const float*)d_in[4];
    const float* b2    = (const float*)d_in[5];
    float* out = (float*)d_out;

    k_fused<<<512, 256>>>(spade, x, w1, w2, b1, b2);
    k_match<<<512, 256>>>(out);
}